// round 16
// baseline (speedup 1.0000x reference)
#include <cuda_runtime.h>
#include <cuda_fp16.h>
#include <math.h>
#include <stdint.h>

#define B_SZ   8
#define C_IN   64
#define HID    256
#define H_SZ   256
#define W_SZ   256
#define THREADS 256
#define NH     32           // hid chunk
#define NCHUNK 8

// pitches (bytes)
#define XPB  144            // 64 c fp16 = 128B + 16 pad
#define HPB  80             // 32 hid fp16 = 64B + 16 pad
#define W1PB 144
#define W2PB 80

// ---------------- smem layout (bytes) ----------------
#define X_OFF    0          // 128 x 144 = 18432
#define H_OFF    18432      // 128 x 80  = 10240
#define W1_OFF   28672      // 2 bufs x 4608
#define W2_OFF   37888      // 2 bufs x 5120
#define B1S_OFF  48128      // 256 f32
#define B2S_OFF  66560      // 64 f32 (beyond overlay; survives epilogue)
#define SMEM_BYTES 66816

// final-phase overlays
// yh[c][win][k]: c-pitch 272B (2-way-max STS), 64*272 = 17408 (over X region)
// Mh[c][m][k]:   m-pitch 48B (conflict-free LDSM), 64*768 = 49152 at 17408
#define YH_OFF  0
#define YHCP    272
#define MH_OFF  17408
#define MHCP    768

// ---------------------------------------------------------------------------
__device__ __forceinline__ uint32_t smem_u32(const void* p) {
    uint32_t a;
    asm("{ .reg .u64 t; cvta.to.shared.u64 t, %1; cvt.u32.u64 %0, t; }" : "=r"(a) : "l"(p));
    return a;
}

#define LDSM4(r0, r1, r2, r3, addr) \
    asm volatile("ldmatrix.sync.aligned.m8n8.x4.shared.b16 {%0,%1,%2,%3}, [%4];" \
        : "=r"(r0), "=r"(r1), "=r"(r2), "=r"(r3) : "r"(addr))

#define LDSM2(r0, r1, addr) \
    asm volatile("ldmatrix.sync.aligned.m8n8.x2.shared.b16 {%0,%1}, [%2];" \
        : "=r"(r0), "=r"(r1) : "r"(addr))

__device__ __forceinline__ void mma16816(float* d, const uint32_t* a, const uint32_t* b) {
    asm volatile(
        "mma.sync.aligned.m16n8k16.row.col.f32.f16.f16.f32 "
        "{%0,%1,%2,%3}, {%4,%5,%6,%7}, {%8,%9}, {%0,%1,%2,%3};"
        : "+f"(d[0]), "+f"(d[1]), "+f"(d[2]), "+f"(d[3])
        : "r"(a[0]), "r"(a[1]), "r"(a[2]), "r"(a[3]), "r"(b[0]), "r"(b[1]));
}

__device__ __forceinline__ void cp16(uint32_t dst, const void* src) {
    asm volatile("cp.async.cg.shared.global [%0], [%1], 16;"
                 :: "r"(dst), "l"(__cvta_generic_to_global(src)) : "memory");
}
__device__ __forceinline__ void cp_commit() {
    asm volatile("cp.async.commit_group;" ::: "memory");
}
template <int N>
__device__ __forceinline__ void cp_wait() {
    asm volatile("cp.async.wait_group %0;" :: "n"(N) : "memory");
}

// Packed half2 GELU (validated r15)
__device__ __forceinline__ uint32_t gelu2(float a0, float a1, __half2 bias) {
    const __half2 cA = __floats2half2_rn(0.7978845608f, 0.7978845608f);
    const __half2 cB = __floats2half2_rn(0.0356774081f, 0.0356774081f);
    __half2 z  = __hadd2(__floats2half2_rn(a0, a1), bias);
    __half2 z2 = __hmul2(z, z);
    __half2 u  = __hmul2(z, __hfma2(cB, z2, cA));
    uint32_t tu;
    asm("tanh.approx.f16x2 %0, %1;" : "=r"(tu) : "r"(*(uint32_t*)&u));
    __half2 t  = *(__half2*)&tu;
    __half2 hz = __hmul2(z, __floats2half2_rn(0.5f, 0.5f));
    __half2 r  = __hfma2(hz, t, hz);
    return *(uint32_t*)&r;
}

// ---------------------------------------------------------------------------
// Precomputed global scratch
// ---------------------------------------------------------------------------
__device__ __half g_Mh[64 * 16 * 24];    // [c][m 16][k 16 + pad 8], 48B rows
__device__ __half g_w1h[HID * C_IN];
__device__ __half g_w2h[C_IN * HID];

// Merged builder: blocks 0..63 mix matrices (padded rows); 64..95 weights
__global__ void build_all_kernel(const float* __restrict__ cw,
                                 const float* __restrict__ w1,
                                 const float* __restrict__ w2) {
    if (blockIdx.x < 64) {
        const int c   = blockIdx.x;
        const int t   = threadIdx.x;
        const int in  = t >> 4;
        const int out = t & 15;
        const int s  = in >> 2, tt = in & 3;
        const int p  = out >> 2, q  = out & 3;
        const float cs[4] = {1.f, 0.f, -1.f, 0.f};
        const float sn[4] = {0.f, 1.f, 0.f, -1.f};
        float tre[3] = {0.f, 0.f, 0.f};
        float tim[3] = {0.f, 0.f, 0.f};
        #pragma unroll
        for (int u = 0; u < 4; ++u) {
            const int e2 = (u * p) & 3;
            const float c2 = cs[e2], s2 = sn[e2];
            #pragma unroll
            for (int v = 0; v < 3; ++v) {
                const int e1 = (4 - ((u * s + v * tt) & 3)) & 3;
                const float yr = 0.25f * cs[e1];
                const float yi = 0.25f * sn[e1];
                const float wr = cw[((u * 3 + v) * 64 + c) * 2 + 0];
                const float wi = cw[((u * 3 + v) * 64 + c) * 2 + 1];
                const float zr = yr * wr - yi * wi;
                const float zi = yr * wi + yi * wr;
                tre[v] += zr * c2 - zi * s2;
                tim[v] += zr * s2 + zi * c2;
            }
        }
        const float sgn = (q & 1) ? -1.f : 1.f;
        const float val =
            0.25f * (tre[0] + sgn * tre[2] + 2.f * (tre[1] * cs[q] - tim[1] * sn[q]));
        g_Mh[c * 384 + out * 24 + in] = __float2half_rn(val);
        if (in >= 8)                                  // zero the pad halfs
            g_Mh[c * 384 + out * 24 + 16 + (in - 8)] = __float2half_rn(0.f);
    } else {
        const int base = (blockIdx.x - 64) * THREADS + threadIdx.x;  // 0..8191
        #pragma unroll
        for (int k = 0; k < 4; ++k) {
            const int i = base + k * 8192;                           // 0..32767
            if (i < HID * C_IN) {
                g_w1h[i] = __float2half_rn(w1[i]);
            } else {
                const int j = i - HID * C_IN;
                g_w2h[j] = __float2half_rn(w2[j]);
            }
        }
    }
}

// ---------------------------------------------------------------------------
// Main kernel
// ---------------------------------------------------------------------------
__global__ __launch_bounds__(THREADS, 3)
void fmffn_kernel(const float* __restrict__ x,
                  const float* __restrict__ b1,
                  const float* __restrict__ b2,
                  float* __restrict__ out) {
    extern __shared__ char smem[];
    const uint32_t sb = smem_u32(smem);

    const int tid  = threadIdx.x;
    const int wid  = tid >> 5;
    const int lane = tid & 31;
    const int b    = blockIdx.z;
    const int h0   = blockIdx.y * 4;
    const int w0   = blockIdx.x * 32;

    float* b1_s = (float*)(smem + B1S_OFF);
    float* b2_s = (float*)(smem + B2S_OFF);

    // per-thread cp.async coordinates
    const int w1row = tid >> 3, w1seg = tid & 7;     // 32 x 8
    const int w2row = tid >> 2, w2seg = tid & 3;     // 64 x 4

    // ---- pre-issue 4 groups: W1(0), W2(0), W1(1), W2(1) ----
    cp16(sb + W1_OFF + w1row * W1PB + w1seg * 16, g_w1h + w1row * 64 + w1seg * 8);
    cp_commit();
    cp16(sb + W2_OFF + w2row * W2PB + w2seg * 16, g_w2h + w2row * 256 + w2seg * 8);
    cp_commit();
    cp16(sb + W1_OFF + 4608 + w1row * W1PB + w1seg * 16,
         g_w1h + NH * 64 + w1row * 64 + w1seg * 8);
    cp_commit();
    cp16(sb + W2_OFF + 5120 + w2row * W2PB + w2seg * 16,
         g_w2h + w2row * 256 + NH + w2seg * 8);
    cp_commit();

    // ---- stage x -> fp16 [pix][c], float4 global loads ----
    for (int i = tid; i < 64 * 4 * 8; i += THREADS) {      // c(64) x r(4) x colgrp(8)
        const int c = i >> 5, r = (i >> 3) & 3, cg = i & 7;
        const float4 v = *(const float4*)&x[
            (((size_t)b * C_IN + c) * H_SZ + (h0 + r)) * W_SZ + w0 + cg * 4];
        char* dst = smem + X_OFF + (r * 32 + cg * 4) * XPB + c * 2;
        *(__half*)(dst)           = __float2half_rn(v.x);
        *(__half*)(dst + XPB)     = __float2half_rn(v.y);
        *(__half*)(dst + 2 * XPB) = __float2half_rn(v.z);
        *(__half*)(dst + 3 * XPB) = __float2half_rn(v.w);
    }
    if (tid < HID)  b1_s[tid] = b1[tid];
    if (tid < C_IN) b2_s[tid] = b2[tid];

    // ---- warp geometry ----
    const int pr  = wid & 3;              // pixel group
    const int wcg = wid >> 2;             // n group
    const int aRow = (lane & 7) + ((lane >> 3) & 1) * 8;
    const int aKof = (lane >> 4) * 8;
    const int bRow = (lane & 7) + (lane >> 4) * 8;
    const int bKof = ((lane >> 3) & 1) * 8;
    const int dRow = lane >> 2;
    const int dCol = (lane & 3) * 2;

    const uint32_t aXbase = sb + X_OFF + (uint32_t)((pr * 32 + aRow) * XPB + aKof * 2);
    const uint32_t aHbase = sb + H_OFF + (uint32_t)((pr * 32 + aRow) * HPB + aKof * 2);
    const uint32_t bW1off = (uint32_t)((wcg * 16 + bRow) * W1PB + bKof * 2);
    const uint32_t bW2off = (uint32_t)((wcg * 32 + bRow) * W2PB + bKof * 2);

    // persistent GEMM2 accumulators: 32 pix x 32 c per warp
    float acc2[2][4][4];
    #pragma unroll
    for (int mt = 0; mt < 2; ++mt)
        #pragma unroll
        for (int nt = 0; nt < 4; ++nt)
            #pragma unroll
            for (int j = 0; j < 4; ++j) acc2[mt][nt][j] = 0.f;

    // ---- 8 hid chunks of 32 ----
    #pragma unroll 1
    for (int nc = 0; nc < NCHUNK; ++nc) {
        const uint32_t w1buf = sb + W1_OFF + (nc & 1) * 4608;
        const uint32_t w2buf = sb + W2_OFF + (nc & 1) * 5120;

        // B1: W1(nc) + W2(nc) arrived; GEMM2(nc-1) retired
        if (nc == 0)                cp_wait<2>();
        else if (nc == NCHUNK - 1)  cp_wait<0>();
        else                        cp_wait<1>();
        __syncthreads();

        // issue W2(nc+1) (buffer parity freed by this B1)
        if (nc >= 1 && nc + 1 < NCHUNK) {
            cp16(sb + W2_OFF + ((nc + 1) & 1) * 5120 + w2row * W2PB + w2seg * 16,
                 g_w2h + w2row * 256 + (nc + 1) * NH + w2seg * 8);
            cp_commit();
        }

        // ===== GEMM1: [128 pix x 32 hid], K = 64, warp tile 32x16 =====
        float acc1[2][2][4];
        #pragma unroll
        for (int mt = 0; mt < 2; ++mt)
            #pragma unroll
            for (int nt = 0; nt < 2; ++nt)
                #pragma unroll
                for (int j = 0; j < 4; ++j) acc1[mt][nt][j] = 0.f;

        #pragma unroll
        for (int ks = 0; ks < 4; ++ks) {
            uint32_t ax[8], bh[4];
            LDSM4(ax[0], ax[1], ax[2], ax[3], aXbase + ks * 32);
            LDSM4(ax[4], ax[5], ax[6], ax[7], aXbase + 16 * XPB + ks * 32);
            LDSM4(bh[0], bh[1], bh[2], bh[3], w1buf + bW1off + ks * 32);
            #pragma unroll
            for (int mt = 0; mt < 2; ++mt)
                #pragma unroll
                for (int nt = 0; nt < 2; ++nt)
                    mma16816(acc1[mt][nt], ax + mt * 4, bh + nt * 2);
        }

        // ---- bias + packed-half2 GELU -> H ----
        #pragma unroll
        for (int nt = 0; nt < 2; ++nt) {
            const int nl = wcg * 16 + nt * 8 + dCol;               // 0..31
            const __half2 bias2 = __floats2half2_rn(b1_s[nc * NH + nl],
                                                    b1_s[nc * NH + nl + 1]);
            #pragma unroll
            for (int mt = 0; mt < 2; ++mt) {
                const int r0 = pr * 32 + mt * 16 + dRow;
                #pragma unroll
                for (int hh = 0; hh < 2; ++hh) {
                    *(uint32_t*)(smem + H_OFF + (r0 + hh * 8) * HPB + nl * 2) =
                        gelu2(acc1[mt][nt][hh * 2 + 0], acc1[mt][nt][hh * 2 + 1], bias2);
                }
            }
        }

        // B3: H visible; all GEMM1(nc) W1-buf reads retired
        __syncthreads();

        // issue W1(nc+2) into buf parity nc&1 (just retired by B3)
        if (nc + 2 < NCHUNK) {
            cp16(w1buf + w1row * W1PB + w1seg * 16,
                 g_w1h + (nc + 2) * NH * 64 + w1row * 64 + w1seg * 8);
            cp_commit();
        }

        // ===== GEMM2: [128 pix x 64 c] += H * W2c^T, K = 32, warp 32x32 =====
        #pragma unroll
        for (int ks = 0; ks < 2; ++ks) {
            uint32_t ah[8], bh[8];
            LDSM4(ah[0], ah[1], ah[2], ah[3], aHbase + ks * 32);
            LDSM4(ah[4], ah[5], ah[6], ah[7], aHbase + 16 * HPB + ks * 32);
            LDSM4(bh[0], bh[1], bh[2], bh[3], w2buf + bW2off + ks * 32);
            LDSM4(bh[4], bh[5], bh[6], bh[7], w2buf + bW2off + 16 * W2PB + ks * 32);
            #pragma unroll
            for (int mt = 0; mt < 2; ++mt)
                #pragma unroll
                for (int nt = 0; nt < 4; ++nt)
                    mma16816(acc2[mt][nt], ah + mt * 4, bh + nt * 2);
        }
    }

    // ---- y (+b2) -> yh overlay over X (GEMM2 reads only H/W2: no barrier) ----
    #pragma unroll
    for (int mt = 0; mt < 2; ++mt)
        #pragma unroll
        for (int nt = 0; nt < 4; ++nt) {
            const int c0 = wcg * 32 + nt * 8 + dCol;
            #pragma unroll
            for (int hh = 0; hh < 2; ++hh) {
                const int col = mt * 16 + hh * 8 + dRow;       // 0..31
                const int win = col >> 2;
                const int kk  = pr * 4 + (col & 3);            // in-patch index
                const uint32_t o = (uint32_t)(win * 32 + kk * 2);
                *(__half*)(smem + YH_OFF + c0 * YHCP + o) =
                    __float2half_rn(acc2[mt][nt][hh * 2 + 0] + b2_s[c0]);
                *(__half*)(smem + YH_OFF + (c0 + 1) * YHCP + o) =
                    __float2half_rn(acc2[mt][nt][hh * 2 + 1] + b2_s[c0 + 1]);
            }
        }

    __syncthreads();                                   // B4: all H/W2 reads done

    // ---- Mh copy into overlay (H/W1/W2/b1 regions dead): 49152B ----
    for (int i = tid; i < 3072; i += THREADS)
        cp16(sb + MH_OFF + i * 16, (const char*)g_Mh + i * 16);
    cp_commit();
    cp_wait<0>();
    __syncthreads();                                   // B5: yh + Mh ready

    // ---- Fourier mix via mma: 8 channels per warp, 1 mma each ----
    const uint32_t aoff = sb + MH_OFF +
        (uint32_t)((((lane & 7) + ((lane >> 3) & 1) * 8) * 24 + ((lane >> 4) & 1) * 8) * 2);
    const uint32_t boff = sb + YH_OFF +
        (uint32_t)(((lane & 7) * 16 + ((lane >> 3) & 1) * 8) * 2);
    const int cb = wid * 8;

    #pragma unroll
    for (int j = 0; j < 8; ++j) {
        const int c = cb + j;
        uint32_t a[4], bb[2];
        LDSM4(a[0], a[1], a[2], a[3], aoff + c * MHCP);
        LDSM2(bb[0], bb[1], boff + c * YHCP);
        float d[4] = {0.f, 0.f, 0.f, 0.f};
        mma16816(d, a, bb);
        const size_t base = (((size_t)(b * C_IN + c)) * H_SZ + h0 + (dRow >> 2)) * W_SZ
                          + w0 + dCol * 4 + (dRow & 3);
        out[base]           = d[0];
        out[base + 4]       = d[1];
        out[base + 2 * 256] = d[2];
        out[base + 2 * 256 + 4] = d[3];
    }
}

// ---------------------------------------------------------------------------
extern "C" void kernel_launch(void* const* d_in, const int* in_sizes, int n_in,
                              void* d_out, int out_size) {
    const float* x  = (const float*)d_in[0];
    const float* w1 = (const float*)d_in[1];
    const float* b1 = (const float*)d_in[2];
    const float* w2 = (const float*)d_in[3];
    const float* b2 = (const float*)d_in[4];
    const float* cw = (const float*)d_in[5];
    float* out = (float*)d_out;

    cudaFuncSetAttribute(fmffn_kernel,
                         cudaFuncAttributeMaxDynamicSharedMemorySize, SMEM_BYTES);

    build_all_kernel<<<96, 256>>>(cw, w1, w2);

    dim3 grid(W_SZ / 32, H_SZ / 4, B_SZ);   // (8, 64, 8)
    fmffn_kernel<<<grid, THREADS, SMEM_BYTES>>>(x, b1, b2, out);
}